// round 14
// baseline (speedup 1.0000x reference)
#include <cuda_runtime.h>
#include <cuda_fp16.h>
#include <cstdint>

#define THREADS 256
#define DEG     16
#define DD      128
#define NPB     128     // nodes per block
#define MAXN    100096

// smem: fp16 A tile (32KB, XOR-swizzled 256B rows) + edge-desc slab (16KB)
#define SM_A     0
#define SM_ED    32768
#define SM_TOTAL 49152

// W in mma-B-fragment layout, fp16 hi/lo interleaved
__device__ uint4 gB[8 * 128 * 4];
// fp16 node features (25.6 MB), row = 16 uint4
__device__ uint4 gFeat16[MAXN * DD / 8];
// packed normalized edges: {col, w/den} per edge (12.8 MB), node-major contiguous
__device__ uint2 gEdgeP[MAXN * DEG];

__device__ __forceinline__ void split_f16(float x, unsigned short& h, unsigned short& l) {
    __half hh = __float2half_rn(x);
    float r = x - __half2float(hh);
    __half ll = __float2half_rn(r);
    h = __half_as_ushort(hh);
    l = __half_as_ushort(ll);
}

__device__ __forceinline__ int a_off(int row, int chunk) {
    return row * 256 + ((chunk ^ (row & 7)) << 4);
}

__device__ __forceinline__ uint32_t smem_u32(const void* p) {
    uint32_t a;
    asm("{ .reg .u64 t; cvta.to.shared.u64 t, %1; cvt.u32.u64 %0, t; }" : "=r"(a) : "l"(p));
    return a;
}

__device__ __forceinline__ void cp_async16(void* smem_dst, const void* gsrc) {
    unsigned int s = (unsigned int)__cvta_generic_to_shared(smem_dst);
    asm volatile("cp.async.cg.shared.global [%0], [%1], 16;\n" :: "r"(s), "l"(gsrc));
}

__device__ __forceinline__ void ldmatrix_x4(uint32_t& r0, uint32_t& r1,
                                            uint32_t& r2, uint32_t& r3, uint32_t addr) {
    asm volatile("ldmatrix.sync.aligned.m8n8.x4.shared.b16 {%0,%1,%2,%3}, [%4];"
                 : "=r"(r0), "=r"(r1), "=r"(r2), "=r"(r3) : "r"(addr));
}

__device__ __forceinline__ void mma_f16(float& d0, float& d1, float& d2, float& d3,
                                        uint32_t a0, uint32_t a1, uint32_t a2, uint32_t a3,
                                        uint32_t b0, uint32_t b1) {
    asm volatile("mma.sync.aligned.m16n8k16.row.col.f32.f16.f16.f32 "
                 "{%0,%1,%2,%3}, {%4,%5,%6,%7}, {%8,%9}, {%0,%1,%2,%3};"
                 : "+f"(d0), "+f"(d1), "+f"(d2), "+f"(d3)
                 : "r"(a0), "r"(a1), "r"(a2), "r"(a3), "r"(b0), "r"(b1));
}

__device__ __forceinline__ void fma2_h2(unsigned long long& acc,
                                        unsigned long long w2, unsigned h2bits) {
    const float2 f = __half22float2(*(const __half2*)&h2bits);
    unsigned long long v;
    asm("mov.b64 %0, {%1, %2};" : "=l"(v) : "f"(f.x), "f"(f.y));
    asm("fma.rn.f32x2 %0, %1, %2, %0;" : "+l"(acc) : "l"(w2), "l"(v));
}
__device__ __forceinline__ void unpack64(unsigned long long v, float& lo, float& hi) {
    asm("mov.b64 {%0, %1}, %2;" : "=f"(lo), "=f"(hi) : "l"(v));
}

__device__ __forceinline__ void stg_cs_f2(float* p, float x, float y) {
    asm volatile("st.global.cs.v2.f32 [%0], {%1, %2};" :: "l"(p), "f"(x), "f"(y) : "memory");
}

// ---- fused prep: feat fp32->fp16 (32 floats/thr) | W fp16-split | edge packing ----
__global__ void __launch_bounds__(256)
prep_all(const float* __restrict__ feat, const float* __restrict__ Wg,
         const int* __restrict__ rows32, const char* __restrict__ cols_raw,
         const float* __restrict__ ew,
         int nblk_feat, int nblk_w, int total32, int N)
{
    const int b = (int)blockIdx.x;
    if (b < nblk_feat) {
        const int i = b * 256 + threadIdx.x;             // unit = 32 floats
        if (i >= total32) return;
        const float4* src = (const float4*)feat + i * 8;
        uint4* dst = gFeat16 + i * 4;
        #pragma unroll
        for (int j = 0; j < 4; j++) {
            float4 v0 = __ldg(src + 2 * j);
            float4 v1 = __ldg(src + 2 * j + 1);
            __half2 a0 = __floats2half2_rn(v0.x, v0.y), a1 = __floats2half2_rn(v0.z, v0.w);
            __half2 a2 = __floats2half2_rn(v1.x, v1.y), a3 = __floats2half2_rn(v1.z, v1.w);
            dst[j] = make_uint4(*(unsigned*)&a0, *(unsigned*)&a1,
                                *(unsigned*)&a2, *(unsigned*)&a3);
        }
    } else if (b < nblk_feat + nblk_w) {
        const int e = (b - nblk_feat) * 256 + threadIdx.x;   // 0..4095
        if (e >= 8 * 128 * 4) return;
        const int kc = e >> 9;
        const int n  = (e >> 2) & 127;
        const int q  = e & 3;
        const int k0 = kc * 16 + 2 * q;
        unsigned short h[4], l[4];
        split_f16(__ldg(Wg + (k0    ) * DD + n), h[0], l[0]);
        split_f16(__ldg(Wg + (k0 + 1) * DD + n), h[1], l[1]);
        split_f16(__ldg(Wg + (k0 + 8) * DD + n), h[2], l[2]);
        split_f16(__ldg(Wg + (k0 + 9) * DD + n), h[3], l[3]);
        gB[e] = make_uint4((unsigned)h[0] | ((unsigned)h[1] << 16),
                           (unsigned)h[2] | ((unsigned)h[3] << 16),
                           (unsigned)l[0] | ((unsigned)l[1] << 16),
                           (unsigned)l[2] | ((unsigned)l[3] << 16));
    } else {
        // edge packing: 64 nodes per block; half-warp per node, lane i = edge i
        const bool idx64 = (__ldg(rows32 + 33) == 0);
        const int li = threadIdx.x & 15;
        #pragma unroll
        for (int j = 0; j < 4; j++) {
            const int node0 = (b - nblk_feat - nblk_w) * 64 + j * 16 + ((int)threadIdx.x >> 4);
            const int node  = min(node0, N - 1);
            const long long ei = (long long)node * DEG + li;
            const int   c = idx64 ? (int)__ldg((const long long*)cols_raw + ei)
                                  : __ldg((const int*)cols_raw + ei);
            const float w = __ldg(ew + ei);
            float den = w;
            den += __shfl_xor_sync(0xffffffffu, den, 1);
            den += __shfl_xor_sync(0xffffffffu, den, 2);
            den += __shfl_xor_sync(0xffffffffu, den, 4);
            den += __shfl_xor_sync(0xffffffffu, den, 8);
            const float wn = w * __fdividef(1.f, den);
            if (node0 < N)
                gEdgeP[(size_t)node * DEG + li] = make_uint2((unsigned)c, __float_as_uint(wn));
        }
    }
}

// ---- fused main: cp.async edge slab -> gather -> smem A tile -> HMMA ----
__global__ void __launch_bounds__(THREADS, 4)
gcn_mma(const float* __restrict__ bias, float* __restrict__ out, int N)
{
    extern __shared__ char smem[];
    const int tid   = threadIdx.x;
    const int wid   = tid >> 5;
    const int lane  = tid & 31;
    const int node0 = blockIdx.x * NPB;

    // ---- Prologue: stage this block's 128-node edge-desc slab (16 KB) ----
    {
        const uint2* src = gEdgeP + (size_t)node0 * DEG;   // contiguous 2048 uint2
        #pragma unroll
        for (int i = 0; i < 4; i++) {
            const int idx = i * 256 + tid;                 // 16B units, 0..1023
            cp_async16(smem + SM_ED + idx * 16, src + idx * 2);
        }
        asm volatile("cp.async.commit_group;" ::: "memory");
        asm volatile("cp.async.wait_group 0;" ::: "memory");
    }
    __syncthreads();

    // ---- Phase 1: mean-aggregate; half-warp per node, lane owns 8 features ----
    const int s  = lane & 15;            // feature slice (8 halves = 1 uint4)
    const int hb = lane >> 4;            // 0: node 2p, 1: node 2p+1
    for (int p = wid; p < NPB / 2; p += 8) {
        const int row = 2 * p + hb;
        const uint4* ed4 = (const uint4*)(smem + SM_ED) + row * (DEG / 2);

        unsigned long long acc[4] = {0ull, 0ull, 0ull, 0ull};
        #pragma unroll
        for (int eg = 0; eg < 4; eg++) {
            // 2 LDS.128 = 4 edges of descs, then 4 independent feature LDG.128s
            const uint4 d01 = ed4[eg * 2];       // {c0, w0, c1, w1}
            const uint4 d23 = ed4[eg * 2 + 1];   // {c2, w2, c3, w3}
            const uint4 v0 = __ldg(gFeat16 + (size_t)d01.x * 16 + s);
            const uint4 v1 = __ldg(gFeat16 + (size_t)d01.z * 16 + s);
            const uint4 v2 = __ldg(gFeat16 + (size_t)d23.x * 16 + s);
            const uint4 v3 = __ldg(gFeat16 + (size_t)d23.z * 16 + s);
            unsigned long long w0, w1, w2, w3;
            asm("mov.b64 %0, {%1, %1};" : "=l"(w0) : "r"(d01.y));
            asm("mov.b64 %0, {%1, %1};" : "=l"(w1) : "r"(d01.w));
            asm("mov.b64 %0, {%1, %1};" : "=l"(w2) : "r"(d23.y));
            asm("mov.b64 %0, {%1, %1};" : "=l"(w3) : "r"(d23.w));
            fma2_h2(acc[0], w0, v0.x);
            fma2_h2(acc[1], w0, v0.y);
            fma2_h2(acc[2], w0, v0.z);
            fma2_h2(acc[3], w0, v0.w);
            fma2_h2(acc[0], w1, v1.x);
            fma2_h2(acc[1], w1, v1.y);
            fma2_h2(acc[2], w1, v1.z);
            fma2_h2(acc[3], w1, v1.w);
            fma2_h2(acc[0], w2, v2.x);
            fma2_h2(acc[1], w2, v2.y);
            fma2_h2(acc[2], w2, v2.z);
            fma2_h2(acc[3], w2, v2.w);
            fma2_h2(acc[0], w3, v3.x);
            fma2_h2(acc[1], w3, v3.y);
            fma2_h2(acc[2], w3, v3.z);
            fma2_h2(acc[3], w3, v3.w);
        }

        float f[8];
        unpack64(acc[0], f[0], f[1]);
        unpack64(acc[1], f[2], f[3]);
        unpack64(acc[2], f[4], f[5]);
        unpack64(acc[3], f[6], f[7]);
        const __half2 p0 = __floats2half2_rn(f[0], f[1]);
        const __half2 p1 = __floats2half2_rn(f[2], f[3]);
        const __half2 p2 = __floats2half2_rn(f[4], f[5]);
        const __half2 p3 = __floats2half2_rn(f[6], f[7]);

        *(uint4*)(smem + SM_A + a_off(row, s)) =
            make_uint4(*(const unsigned*)&p0, *(const unsigned*)&p1,
                       *(const unsigned*)&p2, *(const unsigned*)&p3);
    }
    __syncthreads();

    // ---- Phase 2: warp = 16 rows x 128 cols, as two 16x64 half-tiles ----
    const int m0 = wid * 16;
    const int mi = lane >> 3;
    const int mr = lane & 7;
    const int arow = m0 + ((mi & 1) << 3) + mr;
    const uint32_t sA = smem_u32(smem + SM_A);
    const int bq = (lane >> 2) * 4 + (lane & 3);

    const int r0 = node0 + m0 + (lane >> 2);
    const int cb = 2 * (lane & 3);

    #pragma unroll
    for (int half = 0; half < 2; half++) {
        float acc[8][4];
        #pragma unroll
        for (int nc = 0; nc < 8; nc++)
            acc[nc][0] = acc[nc][1] = acc[nc][2] = acc[nc][3] = 0.f;

        #pragma unroll
        for (int kc = 0; kc < 8; kc++) {
            const int chunk = kc * 2 + (mi >> 1);
            const uint32_t aaddr = (uint32_t)a_off(arow, chunk);
            uint32_t a0, a1, a2, a3;
            ldmatrix_x4(a0, a1, a2, a3, sA + aaddr);

            const uint4* __restrict__ bp = gB + kc * 512 + half * 256 + bq;
            #pragma unroll
            for (int nc = 0; nc < 8; nc++) {
                const uint4 v = __ldg(bp + nc * 32);
                mma_f16(acc[nc][0], acc[nc][1], acc[nc][2], acc[nc][3],
                        a0, a1, a2, a3, v.x, v.y);
                mma_f16(acc[nc][0], acc[nc][1], acc[nc][2], acc[nc][3],
                        a0, a1, a2, a3, v.z, v.w);
            }
        }

        // ---- epilogue for this half: bias + relu + streaming store ----
        #pragma unroll
        for (int nc = 0; nc < 8; nc++) {
            const int col = half * 64 + nc * 8 + cb;
            const float2 bv = __ldg((const float2*)(bias + col));
            if (r0 < N) {
                stg_cs_f2(out + (size_t)r0 * DD + col,
                          fmaxf(acc[nc][0] + bv.x, 0.f),
                          fmaxf(acc[nc][1] + bv.y, 0.f));
            }
            if (r0 + 8 < N) {
                stg_cs_f2(out + (size_t)(r0 + 8) * DD + col,
                          fmaxf(acc[nc][2] + bv.x, 0.f),
                          fmaxf(acc[nc][3] + bv.y, 0.f));
            }
        }
    }
}

extern "C" void kernel_launch(void* const* d_in, const int* in_sizes, int n_in,
                              void* d_out, int out_size)
{
    const float* feat = (const float*)d_in[0];
    const int*   rows = (const int*)d_in[1];
    const char*  cols = (const char*)d_in[2];
    const float* ew   = (const float*)d_in[3];
    const float* Wg   = (const float*)d_in[4];
    const float* bias = (const float*)d_in[5];
    float*       out  = (float*)d_out;

    const int N = in_sizes[0] / DD;

    const int total32   = N * DD / 32;
    const int nblk_feat = (total32 + 255) / 256;
    const int nblk_w    = (8 * 128 * 4 + 255) / 256;
    const int nblk_e    = (N + 63) / 64;
    prep_all<<<nblk_feat + nblk_w + nblk_e, 256>>>(feat, Wg, rows, cols, ew,
                                                   nblk_feat, nblk_w, total32, N);

    cudaFuncSetAttribute(gcn_mma, cudaFuncAttributeMaxDynamicSharedMemorySize, SM_TOTAL);
    gcn_mma<<<(N + NPB - 1) / NPB, THREADS, SM_TOTAL>>>(bias, out, N);
}

// round 15
// speedup vs baseline: 1.0516x; 1.0516x over previous
#include <cuda_runtime.h>
#include <cuda_fp16.h>
#include <cstdint>

#define THREADS 256
#define DEG     16
#define DD      128
#define NPB     128     // nodes per block
#define MAXN    100096

// smem: fp16 A tile (32KB, XOR-swizzled 256B rows) + edge-desc slab (16KB)
#define SM_A     0
#define SM_ED    32768
#define SM_TOTAL 49152

// W in mma-B-fragment layout, fp16 hi/lo interleaved
__device__ uint4 gB[8 * 128 * 4];
// fp16 node features (25.6 MB), row = 16 uint4
__device__ uint4 gFeat16[MAXN * DD / 8];
// packed normalized edges: {col, w/den} per edge (12.8 MB), node-major contiguous
__device__ uint2 gEdgeP[MAXN * DEG];

__device__ __forceinline__ void split_f16(float x, unsigned short& h, unsigned short& l) {
    __half hh = __float2half_rn(x);
    float r = x - __half2float(hh);
    __half ll = __float2half_rn(r);
    h = __half_as_ushort(hh);
    l = __half_as_ushort(ll);
}

__device__ __forceinline__ int a_off(int row, int chunk) {
    return row * 256 + ((chunk ^ (row & 7)) << 4);
}

__device__ __forceinline__ uint32_t smem_u32(const void* p) {
    uint32_t a;
    asm("{ .reg .u64 t; cvta.to.shared.u64 t, %1; cvt.u32.u64 %0, t; }" : "=r"(a) : "l"(p));
    return a;
}

__device__ __forceinline__ void cp_async16(void* smem_dst, const void* gsrc) {
    unsigned int s = (unsigned int)__cvta_generic_to_shared(smem_dst);
    asm volatile("cp.async.cg.shared.global [%0], [%1], 16;\n" :: "r"(s), "l"(gsrc));
}

__device__ __forceinline__ void ldmatrix_x4(uint32_t& r0, uint32_t& r1,
                                            uint32_t& r2, uint32_t& r3, uint32_t addr) {
    asm volatile("ldmatrix.sync.aligned.m8n8.x4.shared.b16 {%0,%1,%2,%3}, [%4];"
                 : "=r"(r0), "=r"(r1), "=r"(r2), "=r"(r3) : "r"(addr));
}

__device__ __forceinline__ void mma_f16(float& d0, float& d1, float& d2, float& d3,
                                        uint32_t a0, uint32_t a1, uint32_t a2, uint32_t a3,
                                        uint32_t b0, uint32_t b1) {
    asm volatile("mma.sync.aligned.m16n8k16.row.col.f32.f16.f16.f32 "
                 "{%0,%1,%2,%3}, {%4,%5,%6,%7}, {%8,%9}, {%0,%1,%2,%3};"
                 : "+f"(d0), "+f"(d1), "+f"(d2), "+f"(d3)
                 : "r"(a0), "r"(a1), "r"(a2), "r"(a3), "r"(b0), "r"(b1));
}

__device__ __forceinline__ void fma2_h2(unsigned long long& acc,
                                        unsigned long long w2, unsigned h2bits) {
    const float2 f = __half22float2(*(const __half2*)&h2bits);
    unsigned long long v;
    asm("mov.b64 %0, {%1, %2};" : "=l"(v) : "f"(f.x), "f"(f.y));
    asm("fma.rn.f32x2 %0, %1, %2, %0;" : "+l"(acc) : "l"(w2), "l"(v));
}
__device__ __forceinline__ void unpack64(unsigned long long v, float& lo, float& hi) {
    asm("mov.b64 {%0, %1}, %2;" : "=f"(lo), "=f"(hi) : "l"(v));
}

__device__ __forceinline__ void stg_cs_f2(float* p, float x, float y) {
    asm volatile("st.global.cs.v2.f32 [%0], {%1, %2};" :: "l"(p), "f"(x), "f"(y) : "memory");
}

// ---- fused prep: feat fp32->fp16 (block-strided coalesced, MLP=8) |
//      W fp16-split | coalesced edge packing ----
__global__ void __launch_bounds__(256)
prep_all(const float* __restrict__ feat, const float* __restrict__ Wg,
         const int* __restrict__ rows32, const char* __restrict__ cols_raw,
         const float* __restrict__ ew,
         int nblk_feat, int nblk_w, int total4, int N)
{
    const int b = (int)blockIdx.x;
    if (b < nblk_feat) {
        // block owns 2048 consecutive float4s; thread t handles base + j*256 + t
        const int base = b * 2048;
        const float4* src = (const float4*)feat;
        uint2* dst = (uint2*)gFeat16;
        #pragma unroll
        for (int j = 0; j < 8; j++) {
            const int idx = base + j * 256 + (int)threadIdx.x;
            if (idx < total4) {
                const float4 v = __ldg(src + idx);
                const __half2 a0 = __floats2half2_rn(v.x, v.y);
                const __half2 a1 = __floats2half2_rn(v.z, v.w);
                dst[idx] = make_uint2(*(const unsigned*)&a0, *(const unsigned*)&a1);
            }
        }
    } else if (b < nblk_feat + nblk_w) {
        const int e = (b - nblk_feat) * 256 + threadIdx.x;   // 0..4095
        if (e >= 8 * 128 * 4) return;
        const int kc = e >> 9;
        const int n  = (e >> 2) & 127;
        const int q  = e & 3;
        const int k0 = kc * 16 + 2 * q;
        unsigned short h[4], l[4];
        split_f16(__ldg(Wg + (k0    ) * DD + n), h[0], l[0]);
        split_f16(__ldg(Wg + (k0 + 1) * DD + n), h[1], l[1]);
        split_f16(__ldg(Wg + (k0 + 8) * DD + n), h[2], l[2]);
        split_f16(__ldg(Wg + (k0 + 9) * DD + n), h[3], l[3]);
        gB[e] = make_uint4((unsigned)h[0] | ((unsigned)h[1] << 16),
                           (unsigned)h[2] | ((unsigned)h[3] << 16),
                           (unsigned)l[0] | ((unsigned)l[1] << 16),
                           (unsigned)l[2] | ((unsigned)l[3] << 16));
    } else {
        // edge packing: 64 nodes per block; half-warp per node, lane i = edge i
        const bool idx64 = (__ldg(rows32 + 33) == 0);
        const int li = threadIdx.x & 15;
        #pragma unroll
        for (int j = 0; j < 4; j++) {
            const int node0 = (b - nblk_feat - nblk_w) * 64 + j * 16 + ((int)threadIdx.x >> 4);
            const int node  = min(node0, N - 1);
            const long long ei = (long long)node * DEG + li;
            const int   c = idx64 ? (int)__ldg((const long long*)cols_raw + ei)
                                  : __ldg((const int*)cols_raw + ei);
            const float w = __ldg(ew + ei);
            float den = w;
            den += __shfl_xor_sync(0xffffffffu, den, 1);
            den += __shfl_xor_sync(0xffffffffu, den, 2);
            den += __shfl_xor_sync(0xffffffffu, den, 4);
            den += __shfl_xor_sync(0xffffffffu, den, 8);
            const float wn = w * __fdividef(1.f, den);
            if (node0 < N)
                gEdgeP[(size_t)node * DEG + li] = make_uint2((unsigned)c, __float_as_uint(wn));
        }
    }
}

// ---- fused main: cp.async edge slab -> gather -> smem A tile -> HMMA ----
__global__ void __launch_bounds__(THREADS, 4)
gcn_mma(const float* __restrict__ bias, float* __restrict__ out, int N)
{
    extern __shared__ char smem[];
    const int tid   = threadIdx.x;
    const int wid   = tid >> 5;
    const int lane  = tid & 31;
    const int node0 = blockIdx.x * NPB;

    // ---- Prologue: stage this block's 128-node edge-desc slab (16 KB) ----
    {
        const uint2* src = gEdgeP + (size_t)node0 * DEG;   // contiguous 2048 uint2
        #pragma unroll
        for (int i = 0; i < 4; i++) {
            const int idx = i * 256 + tid;                 // 16B units, 0..1023
            cp_async16(smem + SM_ED + idx * 16, src + idx * 2);
        }
        asm volatile("cp.async.commit_group;" ::: "memory");
        asm volatile("cp.async.wait_group 0;" ::: "memory");
    }
    __syncthreads();

    // ---- Phase 1: mean-aggregate; half-warp per node, lane owns 8 features ----
    const int s  = lane & 15;            // feature slice (8 halves = 1 uint4)
    const int hb = lane >> 4;            // 0: node 2p, 1: node 2p+1
    for (int p = wid; p < NPB / 2; p += 8) {
        const int row = 2 * p + hb;
        const uint4* ed4 = (const uint4*)(smem + SM_ED) + row * (DEG / 2);

        unsigned long long acc[4] = {0ull, 0ull, 0ull, 0ull};
        #pragma unroll
        for (int eg = 0; eg < 4; eg++) {
            // 2 LDS.128 = 4 edges of descs, then 4 independent feature LDG.128s
            const uint4 d01 = ed4[eg * 2];       // {c0, w0, c1, w1}
            const uint4 d23 = ed4[eg * 2 + 1];   // {c2, w2, c3, w3}
            const uint4 v0 = __ldg(gFeat16 + (size_t)d01.x * 16 + s);
            const uint4 v1 = __ldg(gFeat16 + (size_t)d01.z * 16 + s);
            const uint4 v2 = __ldg(gFeat16 + (size_t)d23.x * 16 + s);
            const uint4 v3 = __ldg(gFeat16 + (size_t)d23.z * 16 + s);
            unsigned long long w0, w1, w2, w3;
            asm("mov.b64 %0, {%1, %1};" : "=l"(w0) : "r"(d01.y));
            asm("mov.b64 %0, {%1, %1};" : "=l"(w1) : "r"(d01.w));
            asm("mov.b64 %0, {%1, %1};" : "=l"(w2) : "r"(d23.y));
            asm("mov.b64 %0, {%1, %1};" : "=l"(w3) : "r"(d23.w));
            fma2_h2(acc[0], w0, v0.x);
            fma2_h2(acc[1], w0, v0.y);
            fma2_h2(acc[2], w0, v0.z);
            fma2_h2(acc[3], w0, v0.w);
            fma2_h2(acc[0], w1, v1.x);
            fma2_h2(acc[1], w1, v1.y);
            fma2_h2(acc[2], w1, v1.z);
            fma2_h2(acc[3], w1, v1.w);
            fma2_h2(acc[0], w2, v2.x);
            fma2_h2(acc[1], w2, v2.y);
            fma2_h2(acc[2], w2, v2.z);
            fma2_h2(acc[3], w2, v2.w);
            fma2_h2(acc[0], w3, v3.x);
            fma2_h2(acc[1], w3, v3.y);
            fma2_h2(acc[2], w3, v3.z);
            fma2_h2(acc[3], w3, v3.w);
        }

        float f[8];
        unpack64(acc[0], f[0], f[1]);
        unpack64(acc[1], f[2], f[3]);
        unpack64(acc[2], f[4], f[5]);
        unpack64(acc[3], f[6], f[7]);
        const __half2 p0 = __floats2half2_rn(f[0], f[1]);
        const __half2 p1 = __floats2half2_rn(f[2], f[3]);
        const __half2 p2 = __floats2half2_rn(f[4], f[5]);
        const __half2 p3 = __floats2half2_rn(f[6], f[7]);

        *(uint4*)(smem + SM_A + a_off(row, s)) =
            make_uint4(*(const unsigned*)&p0, *(const unsigned*)&p1,
                       *(const unsigned*)&p2, *(const unsigned*)&p3);
    }
    __syncthreads();

    // ---- Phase 2: warp = 16 rows x 128 cols, as two 16x64 half-tiles ----
    const int m0 = wid * 16;
    const int mi = lane >> 3;
    const int mr = lane & 7;
    const int arow = m0 + ((mi & 1) << 3) + mr;
    const uint32_t sA = smem_u32(smem + SM_A);
    const int bq = (lane >> 2) * 4 + (lane & 3);

    const int r0 = node0 + m0 + (lane >> 2);
    const int cb = 2 * (lane & 3);

    #pragma unroll
    for (int half = 0; half < 2; half++) {
        float acc[8][4];
        #pragma unroll
        for (int nc = 0; nc < 8; nc++)
            acc[nc][0] = acc[nc][1] = acc[nc][2] = acc[nc][3] = 0.f;

        #pragma unroll
        for (int kc = 0; kc < 8; kc++) {
            const int chunk = kc * 2 + (mi >> 1);
            const uint32_t aaddr = (uint32_t)a_off(arow, chunk);
            uint32_t a0, a1, a2, a3;
            ldmatrix_x4(a0, a1, a2, a3, sA + aaddr);

            const uint4* __restrict__ bp = gB + kc * 512 + half * 256 + bq;
            #pragma unroll
            for (int nc = 0; nc < 8; nc++) {
                const uint4 v = __ldg(bp + nc * 32);
                mma_f16(acc[nc][0], acc[nc][1], acc[nc][2], acc[nc][3],
                        a0, a1, a2, a3, v.x, v.y);
                mma_f16(acc[nc][0], acc[nc][1], acc[nc][2], acc[nc][3],
                        a0, a1, a2, a3, v.z, v.w);
            }
        }

        // ---- epilogue for this half: bias + relu + streaming store ----
        #pragma unroll
        for (int nc = 0; nc < 8; nc++) {
            const int col = half * 64 + nc * 8 + cb;
            const float2 bv = __ldg((const float2*)(bias + col));
            if (r0 < N) {
                stg_cs_f2(out + (size_t)r0 * DD + col,
                          fmaxf(acc[nc][0] + bv.x, 0.f),
                          fmaxf(acc[nc][1] + bv.y, 0.f));
            }
            if (r0 + 8 < N) {
                stg_cs_f2(out + (size_t)(r0 + 8) * DD + col,
                          fmaxf(acc[nc][2] + bv.x, 0.f),
                          fmaxf(acc[nc][3] + bv.y, 0.f));
            }
        }
    }
}

extern "C" void kernel_launch(void* const* d_in, const int* in_sizes, int n_in,
                              void* d_out, int out_size)
{
    const float* feat = (const float*)d_in[0];
    const int*   rows = (const int*)d_in[1];
    const char*  cols = (const char*)d_in[2];
    const float* ew   = (const float*)d_in[3];
    const float* Wg   = (const float*)d_in[4];
    const float* bias = (const float*)d_in[5];
    float*       out  = (float*)d_out;

    const int N = in_sizes[0] / DD;

    const int total4    = N * DD / 4;                    // float4 units
    const int nblk_feat = (total4 + 2047) / 2048;        // 2048 float4s per block
    const int nblk_w    = (8 * 128 * 4 + 255) / 256;
    const int nblk_e    = (N + 63) / 64;
    prep_all<<<nblk_feat + nblk_w + nblk_e, 256>>>(feat, Wg, rows, cols, ew,
                                                   nblk_feat, nblk_w, total4, N);

    cudaFuncSetAttribute(gcn_mma, cudaFuncAttributeMaxDynamicSharedMemorySize, SM_TOTAL);
    gcn_mma<<<(N + NPB - 1) / NPB, THREADS, SM_TOTAL>>>(bias, out, N);
}

// round 16
// speedup vs baseline: 1.0552x; 1.0034x over previous
#include <cuda_runtime.h>
#include <cuda_fp16.h>
#include <cstdint>

#define THREADS 256
#define DEG     16
#define DD      128
#define NPB     128     // nodes per block
#define MAXN    100096

// smem: fp16 A tile (32KB, XOR-swizzled 256B rows) + edge-desc slab (16KB)
#define SM_A     0
#define SM_ED    32768
#define SM_TOTAL 49152

// W in mma-B-fragment layout, fp16 hi/lo interleaved
__device__ uint4 gB[8 * 128 * 4];
// fp16 node features (25.6 MB), row = 16 uint4
__device__ uint4 gFeat16[MAXN * DD / 8];
// packed normalized edges: {col, w/den} per edge (12.8 MB), node-major contiguous
__device__ uint2 gEdgeP[MAXN * DEG];

__device__ __forceinline__ void split_f16(float x, unsigned short& h, unsigned short& l) {
    __half hh = __float2half_rn(x);
    float r = x - __half2float(hh);
    __half ll = __float2half_rn(r);
    h = __half_as_ushort(hh);
    l = __half_as_ushort(ll);
}

__device__ __forceinline__ int a_off(int row, int chunk) {
    return row * 256 + ((chunk ^ (row & 7)) << 4);
}

__device__ __forceinline__ uint32_t smem_u32(const void* p) {
    uint32_t a;
    asm("{ .reg .u64 t; cvta.to.shared.u64 t, %1; cvt.u32.u64 %0, t; }" : "=r"(a) : "l"(p));
    return a;
}

__device__ __forceinline__ void cp_async16(void* smem_dst, const void* gsrc) {
    unsigned int s = (unsigned int)__cvta_generic_to_shared(smem_dst);
    asm volatile("cp.async.cg.shared.global [%0], [%1], 16;\n" :: "r"(s), "l"(gsrc));
}

__device__ __forceinline__ void ldmatrix_x4(uint32_t& r0, uint32_t& r1,
                                            uint32_t& r2, uint32_t& r3, uint32_t addr) {
    asm volatile("ldmatrix.sync.aligned.m8n8.x4.shared.b16 {%0,%1,%2,%3}, [%4];"
                 : "=r"(r0), "=r"(r1), "=r"(r2), "=r"(r3) : "r"(addr));
}

__device__ __forceinline__ void mma_f16(float& d0, float& d1, float& d2, float& d3,
                                        uint32_t a0, uint32_t a1, uint32_t a2, uint32_t a3,
                                        uint32_t b0, uint32_t b1) {
    asm volatile("mma.sync.aligned.m16n8k16.row.col.f32.f16.f16.f32 "
                 "{%0,%1,%2,%3}, {%4,%5,%6,%7}, {%8,%9}, {%0,%1,%2,%3};"
                 : "+f"(d0), "+f"(d1), "+f"(d2), "+f"(d3)
                 : "r"(a0), "r"(a1), "r"(a2), "r"(a3), "r"(b0), "r"(b1));
}

__device__ __forceinline__ void fma2_h2(unsigned long long& acc,
                                        unsigned long long w2, unsigned h2bits) {
    const float2 f = __half22float2(*(const __half2*)&h2bits);
    unsigned long long v;
    asm("mov.b64 %0, {%1, %2};" : "=l"(v) : "f"(f.x), "f"(f.y));
    asm("fma.rn.f32x2 %0, %1, %2, %0;" : "+l"(acc) : "l"(w2), "l"(v));
}
__device__ __forceinline__ void unpack64(unsigned long long v, float& lo, float& hi) {
    asm("mov.b64 {%0, %1}, %2;" : "=f"(lo), "=f"(hi) : "l"(v));
}

__device__ __forceinline__ void stg_cs_f2(float* p, float x, float y) {
    asm volatile("st.global.cs.v2.f32 [%0], {%1, %2};" :: "l"(p), "f"(x), "f"(y) : "memory");
}

// ---- fused prep: feat fp32->fp16 (block-strided coalesced, MLP=8) |
//      W fp16-split | coalesced edge packing ----
__global__ void __launch_bounds__(256)
prep_all(const float* __restrict__ feat, const float* __restrict__ Wg,
         const int* __restrict__ rows32, const char* __restrict__ cols_raw,
         const float* __restrict__ ew,
         int nblk_feat, int nblk_w, int total4, int N)
{
    const int b = (int)blockIdx.x;
    if (b < nblk_feat) {
        // block owns 2048 consecutive float4s; thread t handles base + j*256 + t
        const int base = b * 2048;
        const float4* src = (const float4*)feat;
        uint2* dst = (uint2*)gFeat16;
        #pragma unroll
        for (int j = 0; j < 8; j++) {
            const int idx = base + j * 256 + (int)threadIdx.x;
            if (idx < total4) {
                const float4 v = __ldg(src + idx);
                const __half2 a0 = __floats2half2_rn(v.x, v.y);
                const __half2 a1 = __floats2half2_rn(v.z, v.w);
                dst[idx] = make_uint2(*(const unsigned*)&a0, *(const unsigned*)&a1);
            }
        }
    } else if (b < nblk_feat + nblk_w) {
        const int e = (b - nblk_feat) * 256 + threadIdx.x;   // 0..4095
        if (e >= 8 * 128 * 4) return;
        const int kc = e >> 9;
        const int n  = (e >> 2) & 127;
        const int q  = e & 3;
        const int k0 = kc * 16 + 2 * q;
        unsigned short h[4], l[4];
        split_f16(__ldg(Wg + (k0    ) * DD + n), h[0], l[0]);
        split_f16(__ldg(Wg + (k0 + 1) * DD + n), h[1], l[1]);
        split_f16(__ldg(Wg + (k0 + 8) * DD + n), h[2], l[2]);
        split_f16(__ldg(Wg + (k0 + 9) * DD + n), h[3], l[3]);
        gB[e] = make_uint4((unsigned)h[0] | ((unsigned)h[1] << 16),
                           (unsigned)h[2] | ((unsigned)h[3] << 16),
                           (unsigned)l[0] | ((unsigned)l[1] << 16),
                           (unsigned)l[2] | ((unsigned)l[3] << 16));
    } else {
        // edge packing: 64 nodes per block; half-warp per node, lane i = edge i
        const bool idx64 = (__ldg(rows32 + 33) == 0);
        const int li = threadIdx.x & 15;
        #pragma unroll
        for (int j = 0; j < 4; j++) {
            const int node0 = (b - nblk_feat - nblk_w) * 64 + j * 16 + ((int)threadIdx.x >> 4);
            const int node  = min(node0, N - 1);
            const long long ei = (long long)node * DEG + li;
            const int   c = idx64 ? (int)__ldg((const long long*)cols_raw + ei)
                                  : __ldg((const int*)cols_raw + ei);
            const float w = __ldg(ew + ei);
            float den = w;
            den += __shfl_xor_sync(0xffffffffu, den, 1);
            den += __shfl_xor_sync(0xffffffffu, den, 2);
            den += __shfl_xor_sync(0xffffffffu, den, 4);
            den += __shfl_xor_sync(0xffffffffu, den, 8);
            const float wn = w * __fdividef(1.f, den);
            if (node0 < N)
                gEdgeP[(size_t)node * DEG + li] = make_uint2((unsigned)c, __float_as_uint(wn));
        }
    }
}

// ---- fused main: cp.async edge slab -> pipelined gather -> smem A tile -> HMMA ----
__global__ void __launch_bounds__(THREADS, 4)
gcn_mma(const float* __restrict__ bias, float* __restrict__ out, int N)
{
    extern __shared__ char smem[];
    const int tid   = threadIdx.x;
    const int wid   = tid >> 5;
    const int lane  = tid & 31;
    const int node0 = blockIdx.x * NPB;

    // ---- Prologue: stage this block's 128-node edge-desc slab (16 KB) ----
    {
        const uint2* src = gEdgeP + (size_t)node0 * DEG;   // contiguous 2048 uint2
        #pragma unroll
        for (int i = 0; i < 4; i++) {
            const int idx = i * 256 + tid;                 // 16B units, 0..1023
            cp_async16(smem + SM_ED + idx * 16, src + idx * 2);
        }
        asm volatile("cp.async.commit_group;" ::: "memory");
        asm volatile("cp.async.wait_group 0;" ::: "memory");
    }
    __syncthreads();

    // ---- Phase 1: mean-aggregate; half-warp per node, lane owns 8 features.
    //      Software-pipelined: 8 feature LDG.128s in flight per warp. ----
    const int s  = lane & 15;            // feature slice (8 halves = 1 uint4)
    const int hb = lane >> 4;            // 0: node 2p, 1: node 2p+1
    for (int p = wid; p < NPB / 2; p += 8) {
        const int row = 2 * p + hb;
        const uint4* ed4 = (const uint4*)(smem + SM_ED) + row * (DEG / 2);

        unsigned long long acc[4] = {0ull, 0ull, 0ull, 0ull};

        uint4 d01[2], d23[2];
        uint4 v0[2], v1[2], v2[2], v3[2];

        // prologue: load group 0
        d01[0] = ed4[0];
        d23[0] = ed4[1];
        v0[0] = __ldg(gFeat16 + (size_t)d01[0].x * 16 + s);
        v1[0] = __ldg(gFeat16 + (size_t)d01[0].z * 16 + s);
        v2[0] = __ldg(gFeat16 + (size_t)d23[0].x * 16 + s);
        v3[0] = __ldg(gFeat16 + (size_t)d23[0].z * 16 + s);

        #pragma unroll
        for (int eg = 0; eg < 4; eg++) {
            const int cur = eg & 1, nxt = cur ^ 1;
            if (eg < 3) {
                d01[nxt] = ed4[(eg + 1) * 2];
                d23[nxt] = ed4[(eg + 1) * 2 + 1];
                v0[nxt] = __ldg(gFeat16 + (size_t)d01[nxt].x * 16 + s);
                v1[nxt] = __ldg(gFeat16 + (size_t)d01[nxt].z * 16 + s);
                v2[nxt] = __ldg(gFeat16 + (size_t)d23[nxt].x * 16 + s);
                v3[nxt] = __ldg(gFeat16 + (size_t)d23[nxt].z * 16 + s);
            }
            unsigned long long w0, w1, w2, w3;
            asm("mov.b64 %0, {%1, %1};" : "=l"(w0) : "r"(d01[cur].y));
            asm("mov.b64 %0, {%1, %1};" : "=l"(w1) : "r"(d01[cur].w));
            asm("mov.b64 %0, {%1, %1};" : "=l"(w2) : "r"(d23[cur].y));
            asm("mov.b64 %0, {%1, %1};" : "=l"(w3) : "r"(d23[cur].w));
            fma2_h2(acc[0], w0, v0[cur].x);
            fma2_h2(acc[1], w0, v0[cur].y);
            fma2_h2(acc[2], w0, v0[cur].z);
            fma2_h2(acc[3], w0, v0[cur].w);
            fma2_h2(acc[0], w1, v1[cur].x);
            fma2_h2(acc[1], w1, v1[cur].y);
            fma2_h2(acc[2], w1, v1[cur].z);
            fma2_h2(acc[3], w1, v1[cur].w);
            fma2_h2(acc[0], w2, v2[cur].x);
            fma2_h2(acc[1], w2, v2[cur].y);
            fma2_h2(acc[2], w2, v2[cur].z);
            fma2_h2(acc[3], w2, v2[cur].w);
            fma2_h2(acc[0], w3, v3[cur].x);
            fma2_h2(acc[1], w3, v3[cur].y);
            fma2_h2(acc[2], w3, v3[cur].z);
            fma2_h2(acc[3], w3, v3[cur].w);
        }

        float f[8];
        unpack64(acc[0], f[0], f[1]);
        unpack64(acc[1], f[2], f[3]);
        unpack64(acc[2], f[4], f[5]);
        unpack64(acc[3], f[6], f[7]);
        const __half2 p0 = __floats2half2_rn(f[0], f[1]);
        const __half2 p1 = __floats2half2_rn(f[2], f[3]);
        const __half2 p2 = __floats2half2_rn(f[4], f[5]);
        const __half2 p3 = __floats2half2_rn(f[6], f[7]);

        *(uint4*)(smem + SM_A + a_off(row, s)) =
            make_uint4(*(const unsigned*)&p0, *(const unsigned*)&p1,
                       *(const unsigned*)&p2, *(const unsigned*)&p3);
    }
    __syncthreads();

    // ---- Phase 2: warp = 16 rows x 128 cols, as two 16x64 half-tiles ----
    const int m0 = wid * 16;
    const int mi = lane >> 3;
    const int mr = lane & 7;
    const int arow = m0 + ((mi & 1) << 3) + mr;
    const uint32_t sA = smem_u32(smem + SM_A);
    const int bq = (lane >> 2) * 4 + (lane & 3);

    const int r0 = node0 + m0 + (lane >> 2);
    const int cb = 2 * (lane & 3);

    #pragma unroll
    for (int half = 0; half < 2; half++) {
        float acc[8][4];
        #pragma unroll
        for (int nc = 0; nc < 8; nc++)
            acc[nc][0] = acc[nc][1] = acc[nc][2] = acc[nc][3] = 0.f;

        #pragma unroll
        for (int kc = 0; kc < 8; kc++) {
            const int chunk = kc * 2 + (mi >> 1);
            const uint32_t aaddr = (uint32_t)a_off(arow, chunk);
            uint32_t a0, a1, a2, a3;
            ldmatrix_x4(a0, a1, a2, a3, sA + aaddr);

            const uint4* __restrict__ bp = gB + kc * 512 + half * 256 + bq;
            #pragma unroll
            for (int nc = 0; nc < 8; nc++) {
                const uint4 v = __ldg(bp + nc * 32);
                mma_f16(acc[nc][0], acc[nc][1], acc[nc][2], acc[nc][3],
                        a0, a1, a2, a3, v.x, v.y);
                mma_f16(acc[nc][0], acc[nc][1], acc[nc][2], acc[nc][3],
                        a0, a1, a2, a3, v.z, v.w);
            }
        }

        // ---- epilogue for this half: bias + relu + streaming store ----
        #pragma unroll
        for (int nc = 0; nc < 8; nc++) {
            const int col = half * 64 + nc * 8 + cb;
            const float2 bv = __ldg((const float2*)(bias + col));
            if (r0 < N) {
                stg_cs_f2(out + (size_t)r0 * DD + col,
                          fmaxf(acc[nc][0] + bv.x, 0.f),
                          fmaxf(acc[nc][1] + bv.y, 0.f));
            }
            if (r0 + 8 < N) {
                stg_cs_f2(out + (size_t)(r0 + 8) * DD + col,
                          fmaxf(acc[nc][2] + bv.x, 0.f),
                          fmaxf(acc[nc][3] + bv.y, 0.f));
            }
        }
    }
}

extern "C" void kernel_launch(void* const* d_in, const int* in_sizes, int n_in,
                              void* d_out, int out_size)
{
    const float* feat = (const float*)d_in[0];
    const int*   rows = (const int*)d_in[1];
    const char*  cols = (const char*)d_in[2];
    const float* ew   = (const float*)d_in[3];
    const float* Wg   = (const float*)d_in[4];
    const float* bias = (const float*)d_in[5];
    float*       out  = (float*)d_out;

    const int N = in_sizes[0] / DD;

    const int total4    = N * DD / 4;                    // float4 units
    const int nblk_feat = (total4 + 2047) / 2048;        // 2048 float4s per block
    const int nblk_w    = (8 * 128 * 4 + 255) / 256;
    const int nblk_e    = (N + 63) / 64;
    prep_all<<<nblk_feat + nblk_w + nblk_e, 256>>>(feat, Wg, rows, cols, ew,
                                                   nblk_feat, nblk_w, total4, N);

    cudaFuncSetAttribute(gcn_mma, cudaFuncAttributeMaxDynamicSharedMemorySize, SM_TOTAL);
    gcn_mma<<<(N + NPB - 1) / NPB, THREADS, SM_TOTAL>>>(bias, out, N);
}

// round 17
// speedup vs baseline: 1.1456x; 1.0857x over previous
#include <cuda_runtime.h>
#include <cuda_fp16.h>
#include <cstdint>

#define THREADS 256
#define DEG     16
#define DD      128
#define NPB     64      // nodes per block
#define MAXN    100096

// smem: A tile (16KB) + edge-desc slab (8KB) + per-warp staging ring (32KB)
#define SM_A     0
#define SM_ED    16384
#define SM_ST    24576
#define SM_TOTAL 57344

// W in mma-B-fragment layout, fp16 hi/lo interleaved
__device__ uint4 gB[8 * 128 * 4];
// fp16 node features (25.6 MB), row = 16 uint4
__device__ uint4 gFeat16[MAXN * DD / 8];
// packed normalized edges: {col, w/den} per edge (12.8 MB), node-major contiguous
__device__ uint2 gEdgeP[MAXN * DEG];

__device__ __forceinline__ void split_f16(float x, unsigned short& h, unsigned short& l) {
    __half hh = __float2half_rn(x);
    float r = x - __half2float(hh);
    __half ll = __float2half_rn(r);
    h = __half_as_ushort(hh);
    l = __half_as_ushort(ll);
}

__device__ __forceinline__ int a_off(int row, int chunk) {
    return row * 256 + ((chunk ^ (row & 7)) << 4);
}

__device__ __forceinline__ uint32_t smem_u32(const void* p) {
    uint32_t a;
    asm("{ .reg .u64 t; cvta.to.shared.u64 t, %1; cvt.u32.u64 %0, t; }" : "=r"(a) : "l"(p));
    return a;
}

__device__ __forceinline__ void cp_async16(void* smem_dst, const void* gsrc) {
    unsigned int s = (unsigned int)__cvta_generic_to_shared(smem_dst);
    asm volatile("cp.async.cg.shared.global [%0], [%1], 16;\n" :: "r"(s), "l"(gsrc));
}

__device__ __forceinline__ void ldmatrix_x4(uint32_t& r0, uint32_t& r1,
                                            uint32_t& r2, uint32_t& r3, uint32_t addr) {
    asm volatile("ldmatrix.sync.aligned.m8n8.x4.shared.b16 {%0,%1,%2,%3}, [%4];"
                 : "=r"(r0), "=r"(r1), "=r"(r2), "=r"(r3) : "r"(addr));
}

__device__ __forceinline__ void mma_f16(float& d0, float& d1, float& d2, float& d3,
                                        uint32_t a0, uint32_t a1, uint32_t a2, uint32_t a3,
                                        uint32_t b0, uint32_t b1) {
    asm volatile("mma.sync.aligned.m16n8k16.row.col.f32.f16.f16.f32 "
                 "{%0,%1,%2,%3}, {%4,%5,%6,%7}, {%8,%9}, {%0,%1,%2,%3};"
                 : "+f"(d0), "+f"(d1), "+f"(d2), "+f"(d3)
                 : "r"(a0), "r"(a1), "r"(a2), "r"(a3), "r"(b0), "r"(b1));
}

__device__ __forceinline__ void fma2_h2(unsigned long long& acc,
                                        unsigned long long w2, unsigned h2bits) {
    const float2 f = __half22float2(*(const __half2*)&h2bits);
    unsigned long long v;
    asm("mov.b64 %0, {%1, %2};" : "=l"(v) : "f"(f.x), "f"(f.y));
    asm("fma.rn.f32x2 %0, %1, %2, %0;" : "+l"(acc) : "l"(w2), "l"(v));
}
__device__ __forceinline__ void unpack64(unsigned long long v, float& lo, float& hi) {
    asm("mov.b64 {%0, %1}, %2;" : "=f"(lo), "=f"(hi) : "l"(v));
}

__device__ __forceinline__ void stg_cs_f2(float* p, float x, float y) {
    asm volatile("st.global.cs.v2.f32 [%0], {%1, %2};" :: "l"(p), "f"(x), "f"(y) : "memory");
}

// ---- fused prep: feat fp32->fp16 (block-strided coalesced) | W fp16-split |
//      coalesced edge packing ----
__global__ void __launch_bounds__(256)
prep_all(const float* __restrict__ feat, const float* __restrict__ Wg,
         const int* __restrict__ rows32, const char* __restrict__ cols_raw,
         const float* __restrict__ ew,
         int nblk_feat, int nblk_w, int total4, int N)
{
    const int b = (int)blockIdx.x;
    if (b < nblk_feat) {
        const int base = b * 2048;
        const float4* src = (const float4*)feat;
        uint2* dst = (uint2*)gFeat16;
        #pragma unroll
        for (int j = 0; j < 8; j++) {
            const int idx = base + j * 256 + (int)threadIdx.x;
            if (idx < total4) {
                const float4 v = __ldg(src + idx);
                const __half2 a0 = __floats2half2_rn(v.x, v.y);
                const __half2 a1 = __floats2half2_rn(v.z, v.w);
                dst[idx] = make_uint2(*(const unsigned*)&a0, *(const unsigned*)&a1);
            }
        }
    } else if (b < nblk_feat + nblk_w) {
        const int e = (b - nblk_feat) * 256 + threadIdx.x;
        if (e >= 8 * 128 * 4) return;
        const int kc = e >> 9;
        const int n  = (e >> 2) & 127;
        const int q  = e & 3;
        const int k0 = kc * 16 + 2 * q;
        unsigned short h[4], l[4];
        split_f16(__ldg(Wg + (k0    ) * DD + n), h[0], l[0]);
        split_f16(__ldg(Wg + (k0 + 1) * DD + n), h[1], l[1]);
        split_f16(__ldg(Wg + (k0 + 8) * DD + n), h[2], l[2]);
        split_f16(__ldg(Wg + (k0 + 9) * DD + n), h[3], l[3]);
        gB[e] = make_uint4((unsigned)h[0] | ((unsigned)h[1] << 16),
                           (unsigned)h[2] | ((unsigned)h[3] << 16),
                           (unsigned)l[0] | ((unsigned)l[1] << 16),
                           (unsigned)l[2] | ((unsigned)l[3] << 16));
    } else {
        const bool idx64 = (__ldg(rows32 + 33) == 0);
        const int li = threadIdx.x & 15;
        #pragma unroll
        for (int j = 0; j < 4; j++) {
            const int node0 = (b - nblk_feat - nblk_w) * 64 + j * 16 + ((int)threadIdx.x >> 4);
            const int node  = min(node0, N - 1);
            const long long ei = (long long)node * DEG + li;
            const int   c = idx64 ? (int)__ldg((const long long*)cols_raw + ei)
                                  : __ldg((const int*)cols_raw + ei);
            const float w = __ldg(ew + ei);
            float den = w;
            den += __shfl_xor_sync(0xffffffffu, den, 1);
            den += __shfl_xor_sync(0xffffffffu, den, 2);
            den += __shfl_xor_sync(0xffffffffu, den, 4);
            den += __shfl_xor_sync(0xffffffffu, den, 8);
            const float wn = w * __fdividef(1.f, den);
            if (node0 < N)
                gEdgeP[(size_t)node * DEG + li] = make_uint2((unsigned)c, __float_as_uint(wn));
        }
    }
}

// ---- fused main: cp.async-staged gather (double-buffered) -> A tile -> HMMA ----
__global__ void __launch_bounds__(THREADS, 4)
gcn_mma(const float* __restrict__ bias, float* __restrict__ out, int N)
{
    extern __shared__ char smem[];
    const int tid   = threadIdx.x;
    const int wid   = tid >> 5;
    const int lane  = tid & 31;
    const int node0 = blockIdx.x * NPB;

    // ---- Prologue: stage this block's 64-node edge-desc slab (8 KB) ----
    {
        const uint2* src = gEdgeP + (size_t)node0 * DEG;   // 1024 uint2
        #pragma unroll
        for (int i = 0; i < 2; i++) {
            const int idx = i * 256 + tid;                 // 16B units, 0..511
            cp_async16(smem + SM_ED + idx * 16, src + idx * 2);
        }
        asm volatile("cp.async.commit_group;" ::: "memory");
        asm volatile("cp.async.wait_group 0;" ::: "memory");
    }
    __syncthreads();

    // ---- Phase 1: half-warp per node; features staged via cp.async ring ----
    const int s   = lane & 15;           // feature slice (1 uint4)
    const int hb  = lane >> 4;
    const int l16 = (lane & 15) * 16;
    char* const stw = smem + SM_ST + wid * 4096;   // 2 buffers x 2KB

    for (int p = wid; p < NPB / 2; p += 8) {
        const int row = 2 * p + hb;
        const uint4* ed4 = (const uint4*)(smem + SM_ED) + row * 8;  // 8 uint4/node

        unsigned long long acc[4] = {0ull, 0ull, 0ull, 0ull};
        uint4 d01[2], d23[2];

        // issue group 0 into buffer 0
        d01[0] = ed4[0];
        d23[0] = ed4[1];
        {
            char* dst = stw;
            cp_async16(dst + (0 * 2 + hb) * 256 + l16, gFeat16 + (size_t)d01[0].x * 16 + s);
            cp_async16(dst + (1 * 2 + hb) * 256 + l16, gFeat16 + (size_t)d01[0].z * 16 + s);
            cp_async16(dst + (2 * 2 + hb) * 256 + l16, gFeat16 + (size_t)d23[0].x * 16 + s);
            cp_async16(dst + (3 * 2 + hb) * 256 + l16, gFeat16 + (size_t)d23[0].z * 16 + s);
            asm volatile("cp.async.commit_group;" ::: "memory");
        }

        #pragma unroll
        for (int g = 0; g < 4; g++) {
            const int cur = g & 1, nxt = cur ^ 1;
            if (g < 3) {
                d01[nxt] = ed4[2 * (g + 1)];
                d23[nxt] = ed4[2 * (g + 1) + 1];
                char* dst = stw + nxt * 2048;
                cp_async16(dst + (0 * 2 + hb) * 256 + l16, gFeat16 + (size_t)d01[nxt].x * 16 + s);
                cp_async16(dst + (1 * 2 + hb) * 256 + l16, gFeat16 + (size_t)d01[nxt].z * 16 + s);
                cp_async16(dst + (2 * 2 + hb) * 256 + l16, gFeat16 + (size_t)d23[nxt].x * 16 + s);
                cp_async16(dst + (3 * 2 + hb) * 256 + l16, gFeat16 + (size_t)d23[nxt].z * 16 + s);
                asm volatile("cp.async.commit_group;" ::: "memory");
                asm volatile("cp.async.wait_group 1;" ::: "memory");
            } else {
                asm volatile("cp.async.wait_group 0;" ::: "memory");
            }

            const char* buf = stw + cur * 2048;
            const uint4 v0 = *(const uint4*)(buf + (0 * 2 + hb) * 256 + l16);
            const uint4 v1 = *(const uint4*)(buf + (1 * 2 + hb) * 256 + l16);
            const uint4 v2 = *(const uint4*)(buf + (2 * 2 + hb) * 256 + l16);
            const uint4 v3 = *(const uint4*)(buf + (3 * 2 + hb) * 256 + l16);
            unsigned long long w0, w1, w2, w3;
            asm("mov.b64 %0, {%1, %1};" : "=l"(w0) : "r"(d01[cur].y));
            asm("mov.b64 %0, {%1, %1};" : "=l"(w1) : "r"(d01[cur].w));
            asm("mov.b64 %0, {%1, %1};" : "=l"(w2) : "r"(d23[cur].y));
            asm("mov.b64 %0, {%1, %1};" : "=l"(w3) : "r"(d23[cur].w));
            fma2_h2(acc[0], w0, v0.x);
            fma2_h2(acc[1], w0, v0.y);
            fma2_h2(acc[2], w0, v0.z);
            fma2_h2(acc[3], w0, v0.w);
            fma2_h2(acc[0], w1, v1.x);
            fma2_h2(acc[1], w1, v1.y);
            fma2_h2(acc[2], w1, v1.z);
            fma2_h2(acc[3], w1, v1.w);
            fma2_h2(acc[0], w2, v2.x);
            fma2_h2(acc[1], w2, v2.y);
            fma2_h2(acc[2], w2, v2.z);
            fma2_h2(acc[3], w2, v2.w);
            fma2_h2(acc[0], w3, v3.x);
            fma2_h2(acc[1], w3, v3.y);
            fma2_h2(acc[2], w3, v3.z);
            fma2_h2(acc[3], w3, v3.w);
        }

        float f[8];
        unpack64(acc[0], f[0], f[1]);
        unpack64(acc[1], f[2], f[3]);
        unpack64(acc[2], f[4], f[5]);
        unpack64(acc[3], f[6], f[7]);
        const __half2 p0 = __floats2half2_rn(f[0], f[1]);
        const __half2 p1 = __floats2half2_rn(f[2], f[3]);
        const __half2 p2 = __floats2half2_rn(f[4], f[5]);
        const __half2 p3 = __floats2half2_rn(f[6], f[7]);
        *(uint4*)(smem + SM_A + a_off(row, s)) =
            make_uint4(*(const unsigned*)&p0, *(const unsigned*)&p1,
                       *(const unsigned*)&p2, *(const unsigned*)&p3);
    }
    __syncthreads();

    // ---- Phase 2: warp = 16 rows x 64-col half; 8 warps cover 64x128 ----
    const int half = wid & 1;
    const int m0   = (wid >> 1) * 16;
    const int mi   = lane >> 3;
    const int mr   = lane & 7;
    const int arow = m0 + ((mi & 1) << 3) + mr;
    const uint32_t sA = smem_u32(smem + SM_A);
    const int bq = (lane >> 2) * 4 + (lane & 3);

    const int r0 = node0 + m0 + (lane >> 2);
    const int cb = 2 * (lane & 3);

    float acc[8][4];
    #pragma unroll
    for (int nc = 0; nc < 8; nc++)
        acc[nc][0] = acc[nc][1] = acc[nc][2] = acc[nc][3] = 0.f;

    #pragma unroll
    for (int kc = 0; kc < 8; kc++) {
        const int chunk = kc * 2 + (mi >> 1);
        const uint32_t aaddr = (uint32_t)a_off(arow, chunk);
        uint32_t a0, a1, a2, a3;
        ldmatrix_x4(a0, a1, a2, a3, sA + aaddr);

        const uint4* __restrict__ bp = gB + kc * 512 + half * 256 + bq;
        #pragma unroll
        for (int nc = 0; nc < 8; nc++) {
            const uint4 v = __ldg(bp + nc * 32);
            mma_f16(acc[nc][0], acc[nc][1], acc[nc][2], acc[nc][3],
                    a0, a1, a2, a3, v.x, v.y);
            mma_f16(acc[nc][0], acc[nc][1], acc[nc][2], acc[nc][3],
                    a0, a1, a2, a3, v.z, v.w);
        }
    }

    #pragma unroll
    for (int nc = 0; nc < 8; nc++) {
        const int col = half * 64 + nc * 8 + cb;
        const float2 bv = __ldg((const float2*)(bias + col));
        if (r0 < N) {
            stg_cs_f2(out + (size_t)r0 * DD + col,
                      fmaxf(acc[nc][0] + bv.x, 0.f),
                      fmaxf(acc[nc][1] + bv.y, 0.f));
        }
        if (r0 + 8 < N) {
            stg_cs_f2(out + (size_t)(r0 + 8) * DD + col,
                      fmaxf(acc[nc][2] + bv.x, 0.f),
                      fmaxf(acc[nc][3] + bv.y, 0.f));
        }
    }
}

extern "C" void kernel_launch(void* const* d_in, const int* in_sizes, int n_in,
                              void* d_out, int out_size)
{
    const float* feat = (const float*)d_in[0];
    const int*   rows = (const int*)d_in[1];
    const char*  cols = (const char*)d_in[2];
    const float* ew   = (const float*)d_in[3];
    const float* Wg   = (const float*)d_in[4];
    const float* bias = (const float*)d_in[5];
    float*       out  = (float*)d_out;

    const int N = in_sizes[0] / DD;

    const int total4    = N * DD / 4;
    const int nblk_feat = (total4 + 2047) / 2048;
    const int nblk_w    = (8 * 128 * 4 + 255) / 256;
    const int nblk_e    = (N + 63) / 64;
    prep_all<<<nblk_feat + nblk_w + nblk_e, 256>>>(feat, Wg, rows, cols, ew,
                                                   nblk_feat, nblk_w, total4, N);

    cudaFuncSetAttribute(gcn_mma, cudaFuncAttributeMaxDynamicSharedMemorySize, SM_TOTAL);
    gcn_mma<<<(N + NPB - 1) / NPB, THREADS, SM_TOTAL>>>(bias, out, N);
}